// round 5
// baseline (speedup 1.0000x reference)
#include <cuda_runtime.h>
#include <cstdint>
#include <cstddef>

typedef unsigned long long u64;
typedef unsigned int u32;

#define NN 100000
#define NE 3200000
#define DD 32
#define L2E 1.4426950408889634f

// ---------- scratch (no dynamic alloc allowed) ----------
__device__ __align__(16) float g_Ps[(size_t)NN * DD];
__device__ __align__(16) float g_Pd[(size_t)NN * DD];
__device__ __align__(16) float g_scores[NE];
__device__ u32   g_min_ord;
__device__ u32   g_maxU_ord;
__device__ float g_minf;
__device__ float g_mmax;
__device__ float g_sum;
__device__ float g_inv;

// ---------- helpers ----------
__device__ __forceinline__ u32 ford(float f) {
    u32 u = __float_as_uint(f);
    return (u & 0x80000000u) ? ~u : (u | 0x80000000u);
}
__device__ __forceinline__ float orf(u32 o) {
    u32 u = (o & 0x80000000u) ? (o ^ 0x80000000u) : ~o;
    return __uint_as_float(u);
}
__device__ __forceinline__ u64 pk2(float x) {
    u64 r; u32 a = __float_as_uint(x);
    asm("mov.b64 %0, {%1, %1};" : "=l"(r) : "r"(a));
    return r;
}
__device__ __forceinline__ u64 pk2b(float x, float y) {
    u64 r; u32 a = __float_as_uint(x), b = __float_as_uint(y);
    asm("mov.b64 %0, {%1, %2};" : "=l"(r) : "r"(a), "r"(b));
    return r;
}
#define FMA2(acc, a, b) asm("fma.rn.f32x2 %0, %1, %2, %0;" : "+l"(acc) : "l"(a), "l"(b))
#define ADD2(acc, b)    asm("add.rn.f32x2 %0, %0, %1;"     : "+l"(acc) : "l"(b))

__device__ __forceinline__ void lds2(u64& a, u64& b, u32 addr) {
    asm("ld.shared.v2.u64 {%0, %1}, [%2];" : "=l"(a), "=l"(b) : "r"(addr));
}
__device__ __forceinline__ void ldg2(u64& a, u64& b, const void* p) {
    asm("ld.global.nc.v2.u64 {%0, %1}, [%2];" : "=l"(a), "=l"(b) : "l"(p));
}
__device__ __forceinline__ float ex2a(float x) {
    float y; asm("ex2.approx.ftz.f32 %0, %1;" : "=f"(y) : "f"(x)); return y;
}
__device__ __forceinline__ float lo2(u64 v) { return __uint_as_float((u32)v); }
__device__ __forceinline__ float hi2(u64 v) { return __uint_as_float((u32)(v >> 32)); }

// ---------- kernels ----------
__global__ void k_init() {
    g_min_ord  = 0xFFFFFFFFu;
    g_maxU_ord = 0u;
    g_sum = 0.0f;
}

// Ps[n] = node_reps[n] @ W[0:32], Pd[n] = node_reps[n] @ W[32:64]
__global__ void __launch_bounds__(256) k_node(const float* __restrict__ node_reps,
                                              const float* __restrict__ W) {
    __shared__ __align__(16) u64 sW[64 * 16];   // W rows 0..63, as float pairs
    const u64* Wu = (const u64*)W;
    for (int i = threadIdx.x; i < 64 * 16; i += 256) sW[i] = Wu[i];
    __syncthreads();

    int n = blockIdx.x * 256 + threadIdx.x;
    if (n >= NN) return;

    float nv[32];
    const float4* np = (const float4*)(node_reps + (size_t)n * DD);
#pragma unroll
    for (int q = 0; q < 8; q++) {
        float4 t = np[q];
        nv[4*q+0] = t.x; nv[4*q+1] = t.y; nv[4*q+2] = t.z; nv[4*q+3] = t.w;
    }
    u32 sbase = (u32)__cvta_generic_to_shared(sW);

#pragma unroll
    for (int half = 0; half < 2; half++) {
        u64 acc[16];
#pragma unroll
        for (int jp = 0; jp < 16; jp++) acc[jp] = 0ull;  // (0.0f, 0.0f)
#pragma unroll
        for (int k = 0; k < 32; k++) {
            u64 ek2 = pk2(nv[k]);
            u32 row = sbase + (u32)(half * 32 + k) * 128u;
#pragma unroll
            for (int q = 0; q < 8; q++) {
                u64 w0, w1; lds2(w0, w1, row + q * 16u);
                FMA2(acc[2*q + 0], ek2, w0);
                FMA2(acc[2*q + 1], ek2, w1);
            }
        }
        u64* dst = (u64*)((half == 0 ? g_Ps : g_Pd) + (size_t)n * DD);
#pragma unroll
        for (int jp = 0; jp < 16; jp++) dst[jp] = acc[jp];
    }
}

// per-edge: z = Ps[src] + Pd[dst] + e@We + b ; a = elu(z); s = a.(g-sg)
// also block-reduce: min(s) over all, max(s) over unselected
__global__ void __launch_bounds__(256) k_edge(const float* __restrict__ edge_reps,
                                              const int* __restrict__ ei,
                                              const int* __restrict__ sel,
                                              const float* __restrict__ W,
                                              const float* __restrict__ b,
                                              const float* __restrict__ graph_rep,
                                              const float* __restrict__ sub_rep) {
    __shared__ __align__(16) u64 sW[32 * 16];   // W rows 64..95 (edge block)
    __shared__ __align__(16) u64 sb2[16];
    __shared__ __align__(16) u64 sg2[16];
    __shared__ float rmin[256];
    __shared__ float rmax[256];

    const u64* Wu = (const u64*)W;
    int t = threadIdx.x;
    for (int i = t; i < 32 * 16; i += 256) sW[i] = Wu[64 * 16 + i];
    if (t < 16) sb2[t] = ((const u64*)b)[t];
    if (t < 16) {
        int j = t * 2;
        float a = graph_rep[j]     - sub_rep[j];
        float c = graph_rep[j + 1] - sub_rep[j + 1];
        sg2[t] = pk2b(a, c);
    }
    __syncthreads();

    int e = blockIdx.x * 256 + t;   // grid covers NE exactly

    float er[32];
    const float4* ep = (const float4*)(edge_reps + (size_t)e * DD);
#pragma unroll
    for (int q = 0; q < 8; q++) {
        float4 v = ep[q];
        er[4*q+0] = v.x; er[4*q+1] = v.y; er[4*q+2] = v.z; er[4*q+3] = v.w;
    }
    int src = ei[e];
    int dst = ei[NE + e];

    u64 acc[16];
#pragma unroll
    for (int jp = 0; jp < 16; jp++) acc[jp] = sb2[jp];

    u32 sbase = (u32)__cvta_generic_to_shared(sW);
#pragma unroll
    for (int k = 0; k < 32; k++) {
        u64 ek2 = pk2(er[k]);
        u32 row = sbase + (u32)k * 128u;
#pragma unroll
        for (int q = 0; q < 8; q++) {
            u64 w0, w1; lds2(w0, w1, row + q * 16u);
            FMA2(acc[2*q + 0], ek2, w0);
            FMA2(acc[2*q + 1], ek2, w1);
        }
    }

    const char* ps = (const char*)(g_Ps + (size_t)src * DD);
    const char* pd = (const char*)(g_Pd + (size_t)dst * DD);
#pragma unroll
    for (int q = 0; q < 8; q++) {
        u64 a0, a1; ldg2(a0, a1, ps + q * 16);
        ADD2(acc[2*q + 0], a0);
        ADD2(acc[2*q + 1], a1);
    }
#pragma unroll
    for (int q = 0; q < 8; q++) {
        u64 a0, a1; ldg2(a0, a1, pd + q * 16);
        ADD2(acc[2*q + 0], a0);
        ADD2(acc[2*q + 1], a1);
    }

    // ELU + dot with g
    u64 sacc = 0ull;
#pragma unroll
    for (int jp = 0; jp < 16; jp++) {
        float zlo = lo2(acc[jp]);
        float zhi = hi2(acc[jp]);
        float alo = zlo; if (zlo < 0.0f) alo = ex2a(zlo * L2E) - 1.0f;
        float ahi = zhi; if (zhi < 0.0f) ahi = ex2a(zhi * L2E) - 1.0f;
        u64 ap = pk2b(alo, ahi);
        u64 gp = sg2[jp];
        FMA2(sacc, ap, gp);
    }
    float s = lo2(sacc) + hi2(sacc);

    g_scores[e] = s;
    bool is_sel = (sel[e] != 0);
    float NEG_INF = __int_as_float(0xff800000);

    rmin[t] = s;
    rmax[t] = is_sel ? NEG_INF : s;
    __syncthreads();
#pragma unroll
    for (int o = 128; o > 0; o >>= 1) {
        if (t < o) {
            rmin[t] = fminf(rmin[t], rmin[t + o]);
            rmax[t] = fmaxf(rmax[t], rmax[t + o]);
        }
        __syncthreads();
    }
    if (t == 0) {
        atomicMin(&g_min_ord,  ford(rmin[0]));
        atomicMax(&g_maxU_ord, ford(rmax[0]));
    }
}

__global__ void k_fin() {
    float mn = orf(g_min_ord);
    g_minf = mn;
    g_mmax = fmaxf(mn, orf(g_maxU_ord));
}

__global__ void __launch_bounds__(256) k_exp(const int* __restrict__ sel,
                                             float* __restrict__ out) {
    __shared__ float rs[256];
    int t = threadIdx.x;
    int e = blockIdx.x * 256 + t;
    float mn = g_minf;
    float mx = g_mmax;
    float s = g_scores[e];
    if (sel[e] != 0) s = mn;
    // exp((s - mx)/T), T = 0.5  ->  exp2((s - mx) * 2 * log2(e))
    float v = ex2a((s - mx) * (2.0f * L2E));
    out[e] = v;
    rs[t] = v;
    __syncthreads();
#pragma unroll
    for (int o = 128; o > 0; o >>= 1) {
        if (t < o) rs[t] += rs[t + o];
        __syncthreads();
    }
    if (t == 0) atomicAdd(&g_sum, rs[0]);
}

__global__ void k_inv() { g_inv = 1.0f / g_sum; }

__global__ void __launch_bounds__(256) k_scale(float* __restrict__ out) {
    int i = blockIdx.x * 256 + threadIdx.x;   // in float4 units
    float4* o4 = (float4*)out;
    float inv = g_inv;
    float4 v = o4[i];
    v.x *= inv; v.y *= inv; v.z *= inv; v.w *= inv;
    o4[i] = v;
}

// ---------- launch ----------
extern "C" void kernel_launch(void* const* d_in, const int* in_sizes, int n_in,
                              void* d_out, int out_size) {
    const float*         node_reps = (const float*)d_in[0];
    const float*         edge_reps = (const float*)d_in[1];
    const float*         graph_rep = (const float*)d_in[2];
    const float*         sub_rep   = (const float*)d_in[3];
    const float*         W         = (const float*)d_in[4];
    const float*         b         = (const float*)d_in[5];
    const int*           ei        = (const int*)d_in[6];
    const int*           sel       = (const int*)d_in[7];
    float* out = (float*)d_out;

    k_init<<<1, 1>>>();
    k_node<<<(NN + 255) / 256, 256>>>(node_reps, W);
    k_edge<<<NE / 256, 256>>>(edge_reps, ei, sel, W, b, graph_rep, sub_rep);
    k_fin<<<1, 1>>>();
    k_exp<<<NE / 256, 256>>>(sel, out);
    k_inv<<<1, 1>>>();
    k_scale<<<NE / 1024, 256>>>(out);
}

// round 9
// speedup vs baseline: 1.6934x; 1.6934x over previous
#include <cuda_runtime.h>
#include <cstdint>
#include <cstddef>

typedef unsigned long long u64;
typedef unsigned int u32;

#define NN 100000
#define NE 3200000
#define DD 32
#define L2E 1.4426950408889634f
#define EWARPS 4            // warps per block in k_edge
#define ERB_U64 1056        // per-warp staging buffer: 8448B (64 rows x 33 floats)

// ---------- scratch ----------
__device__ __align__(16) float g_Ps[(size_t)NN * DD];
__device__ __align__(16) float g_Pd[(size_t)NN * DD];
__device__ __align__(16) float g_scores[NE];
__device__ u32   g_min_ord;
__device__ u32   g_maxU_ord;
__device__ float g_sum;

// ---------- helpers ----------
__device__ __forceinline__ u32 ford(float f) {
    u32 u = __float_as_uint(f);
    return (u & 0x80000000u) ? ~u : (u | 0x80000000u);
}
__device__ __forceinline__ float orf(u32 o) {
    u32 u = (o & 0x80000000u) ? (o ^ 0x80000000u) : ~o;
    return __uint_as_float(u);
}
__device__ __forceinline__ u64 pk2(float x) {
    u64 r; u32 a = __float_as_uint(x);
    asm("mov.b64 %0, {%1, %1};" : "=l"(r) : "r"(a));
    return r;
}
__device__ __forceinline__ u64 pk2b(float x, float y) {
    u64 r; u32 a = __float_as_uint(x), b = __float_as_uint(y);
    asm("mov.b64 %0, {%1, %2};" : "=l"(r) : "r"(a), "r"(b));
    return r;
}
#define FMA2(acc, a, b) asm("fma.rn.f32x2 %0, %1, %2, %0;" : "+l"(acc) : "l"(a), "l"(b))
#define ADD2(acc, b)    asm("add.rn.f32x2 %0, %0, %1;"     : "+l"(acc) : "l"(b))

// Non-volatile: ONLY for buffers written once before __syncthreads (sW/sb2/sg2).
__device__ __forceinline__ void lds2(u64& a, u64& b, u32 addr) {
    asm("ld.shared.v2.u64 {%0, %1}, [%2];" : "=l"(a), "=l"(b) : "r"(addr));
}
// Volatile + memory clobber: for staged buffers that are rewritten between reads.
__device__ __forceinline__ void lds2v(u64& a, u64& b, u32 addr) {
    asm volatile("ld.shared.v2.u64 {%0, %1}, [%2];" : "=l"(a), "=l"(b) : "r"(addr) : "memory");
}
__device__ __forceinline__ void sts2(u32 addr, u64 a, u64 b) {
    asm volatile("st.shared.v2.u64 [%0], {%1, %2};" :: "r"(addr), "l"(a), "l"(b) : "memory");
}
__device__ __forceinline__ float ldsfv(u32 addr) {
    float v; asm volatile("ld.shared.f32 %0, [%1];" : "=f"(v) : "r"(addr) : "memory"); return v;
}
__device__ __forceinline__ void stsfv(u32 addr, float v) {
    asm volatile("st.shared.f32 [%0], %1;" :: "r"(addr), "f"(v) : "memory");
}
__device__ __forceinline__ void ldg2(u64& a, u64& b, const void* p) {
    asm("ld.global.nc.v2.u64 {%0, %1}, [%2];" : "=l"(a), "=l"(b) : "l"(p));
}
__device__ __forceinline__ float ex2a(float x) {
    float y; asm("ex2.approx.ftz.f32 %0, %1;" : "=f"(y) : "f"(x)); return y;
}
__device__ __forceinline__ float lo2(u64 v) { return __uint_as_float((u32)v); }
__device__ __forceinline__ float hi2(u64 v) { return __uint_as_float((u32)(v >> 32)); }

// ---------- k_node: Ps/Pd precompute (+ global init) ----------
__global__ void __launch_bounds__(256) k_node(const float* __restrict__ node_reps,
                                              const float* __restrict__ W) {
    if (blockIdx.x == 0 && threadIdx.x == 0) {
        g_min_ord  = 0xFFFFFFFFu;
        g_maxU_ord = 0u;
        g_sum = 0.0f;
    }
    __shared__ __align__(16) u64 sW[64 * 16];
    const u64* Wu = (const u64*)W;
    for (int i = threadIdx.x; i < 64 * 16; i += 256) sW[i] = Wu[i];
    __syncthreads();

    int n = blockIdx.x * 256 + threadIdx.x;
    if (n >= NN) return;

    float nv[32];
    const float4* np = (const float4*)(node_reps + (size_t)n * DD);
#pragma unroll
    for (int q = 0; q < 8; q++) {
        float4 t = np[q];
        nv[4*q+0] = t.x; nv[4*q+1] = t.y; nv[4*q+2] = t.z; nv[4*q+3] = t.w;
    }
    u32 sbase = (u32)__cvta_generic_to_shared(sW);

#pragma unroll
    for (int half = 0; half < 2; half++) {
        u64 acc[16];
#pragma unroll
        for (int jp = 0; jp < 16; jp++) acc[jp] = 0ull;
#pragma unroll
        for (int k = 0; k < 32; k++) {
            u64 ek2 = pk2(nv[k]);
            u32 row = sbase + (u32)(half * 32 + k) * 128u;
#pragma unroll
            for (int q = 0; q < 8; q++) {
                u64 w0, w1; lds2(w0, w1, row + q * 16u);
                FMA2(acc[2*q + 0], ek2, w0);
                FMA2(acc[2*q + 1], ek2, w1);
            }
        }
        u64* dst = (u64*)((half == 0 ? g_Ps : g_Pd) + (size_t)n * DD);
#pragma unroll
        for (int jp = 0; jp < 16; jp++) dst[jp] = acc[jp];
    }
}

// ---------- k_edge: 128 thr, 4 warps, 64 edges/warp (2 per thread) ----------
__global__ void __launch_bounds__(128) k_edge(const float* __restrict__ edge_reps,
                                              const int* __restrict__ ei,
                                              const int* __restrict__ sel,
                                              const float* __restrict__ W,
                                              const float* __restrict__ b,
                                              const float* __restrict__ graph_rep,
                                              const float* __restrict__ sub_rep) {
    __shared__ __align__(16) u64 sW[32 * 16];
    __shared__ __align__(16) u64 sb2[16];
    __shared__ __align__(16) u64 sg2[16];
    __shared__ float sred[2 * EWARPS];
    __shared__ __align__(16) u64 sbuf[EWARPS][ERB_U64];

    const u64* Wu = (const u64*)W;
    int t = threadIdx.x;
    int w = t >> 5;
    int lane = t & 31;

    for (int i = t; i < 32 * 16; i += 128) sW[i] = Wu[64 * 16 + i];
    if (t < 16) sb2[t] = ((const u64*)b)[t];
    else if (t >= 32 && t < 48) {
        int j = (t - 32) * 2;
        sg2[t - 32] = pk2b(graph_rep[j] - sub_rep[j], graph_rep[j+1] - sub_rep[j+1]);
    }
    __syncthreads();

    const size_t base = (size_t)(blockIdx.x * EWARPS + w) * 64;  // 64 edges per warp

    u32 gbase = (u32)__cvta_generic_to_shared(sbuf[w]);

    // --- cooperative load of 64 edge rows (8KB) into smem, stride 33 floats ---
    // Scalar STS: (r*33 + c8*4)*4 is NOT 16B-aligned for r%4!=0, so no vector store.
    const float4* ersrc = (const float4*)(edge_reps + base * DD);
    int d8 = lane >> 3, c8 = lane & 7;
#pragma unroll
    for (int i = 0; i < 16; i++) {
        int r = 4 * i + d8;
        float4 v = __ldg(&ersrc[r * 8 + c8]);
        u32 dp = gbase + (u32)(r * 33 + c8 * 4) * 4u;
        stsfv(dp +  0u, v.x);
        stsfv(dp +  4u, v.y);
        stsfv(dp +  8u, v.z);
        stsfv(dp + 12u, v.w);
    }
    int idx4[4];
    idx4[0] = ei[base + lane];            // src of edge0
    idx4[1] = ei[NE + base + lane];       // dst of edge0
    idx4[2] = ei[base + 32 + lane];       // src of edge1
    idx4[3] = ei[NE + base + 32 + lane];  // dst of edge1
    int sel0 = sel[base + lane];
    int sel1 = sel[base + 32 + lane];
    __syncwarp();

    // --- GEMM: 2 edges per thread, W broadcast from smem ---
    u64 acc0[16], acc1[16];
#pragma unroll
    for (int jp = 0; jp < 16; jp++) { acc0[jp] = sb2[jp]; acc1[jp] = sb2[jp]; }

    u32 sWb = (u32)__cvta_generic_to_shared(sW);
    u32 er0a = gbase + (u32)(lane * 33) * 4u;
    u32 er1a = gbase + (u32)((lane + 32) * 33) * 4u;
#pragma unroll
    for (int k = 0; k < 32; k++) {
        u64 e0 = pk2(ldsfv(er0a + 4u * k));
        u64 e1 = pk2(ldsfv(er1a + 4u * k));
        u32 row = sWb + (u32)k * 128u;
#pragma unroll
        for (int q = 0; q < 8; q++) {
            u64 w0, w1; lds2(w0, w1, row + q * 16u);
            FMA2(acc0[2*q + 0], e0, w0);
            FMA2(acc0[2*q + 1], e0, w1);
            FMA2(acc1[2*q + 0], e1, w0);
            FMA2(acc1[2*q + 1], e1, w1);
        }
    }
    __syncwarp();   // done reading er buffer; reuse it for gathers

    // --- 4 cooperative gather passes (src0, dst0, src1, dst1), stride 18 u64 ---
#pragma unroll
    for (int p = 0; p < 4; p++) {
        const float* table = (p & 1) ? g_Pd : g_Ps;
        int myidx = idx4[p];
#pragma unroll
        for (int i = 0; i < 8; i++) {
            int r = 4 * i + d8;
            int ridx = __shfl_sync(0xffffffffu, myidx, r);
            const char* gp = (const char*)table + (size_t)ridx * 128 + c8 * 16;
            u64 a0, a1; ldg2(a0, a1, gp);
            sts2(gbase + (u32)(18 * r + 2 * c8) * 8u, a0, a1);
        }
        __syncwarp();
        u32 rowa = gbase + (u32)lane * 144u;
        u64* acc = (p < 2) ? acc0 : acc1;
#pragma unroll
        for (int q = 0; q < 8; q++) {
            u64 a0, a1; lds2v(a0, a1, rowa + 16u * q);   // volatile: NO CSE across passes
            ADD2(acc[2*q + 0], a0);
            ADD2(acc[2*q + 1], a1);
        }
        __syncwarp();
    }

    // --- ELU + dot with (g - sg) for both edges ---
    float s01[2];
#pragma unroll
    for (int eidx = 0; eidx < 2; eidx++) {
        u64* acc = eidx ? acc1 : acc0;
        u64 sacc = 0ull;
#pragma unroll
        for (int jp = 0; jp < 16; jp++) {
            float zlo = lo2(acc[jp]);
            float zhi = hi2(acc[jp]);
            float alo = zlo; if (zlo < 0.0f) alo = ex2a(zlo * L2E) - 1.0f;
            float ahi = zhi; if (zhi < 0.0f) ahi = ex2a(zhi * L2E) - 1.0f;
            FMA2(sacc, pk2b(alo, ahi), sg2[jp]);
        }
        s01[eidx] = lo2(sacc) + hi2(sacc);
    }
    g_scores[base + lane]      = s01[0];
    g_scores[base + 32 + lane] = s01[1];

    // --- reductions: warp shfl, then cross-warp via smem, one atomic pair ---
    float NEG_INF = __int_as_float(0xff800000);
    float mymin = fminf(s01[0], s01[1]);
    float mymax = fmaxf(sel0 ? NEG_INF : s01[0], sel1 ? NEG_INF : s01[1]);
#pragma unroll
    for (int o = 16; o > 0; o >>= 1) {
        mymin = fminf(mymin, __shfl_xor_sync(0xffffffffu, mymin, o));
        mymax = fmaxf(mymax, __shfl_xor_sync(0xffffffffu, mymax, o));
    }
    if (lane == 0) { sred[w] = mymin; sred[EWARPS + w] = mymax; }
    __syncthreads();
    if (t == 0) {
        float bmin = sred[0], bmax = sred[EWARPS];
#pragma unroll
        for (int i = 1; i < EWARPS; i++) {
            bmin = fminf(bmin, sred[i]);
            bmax = fmaxf(bmax, sred[EWARPS + i]);
        }
        atomicMin(&g_min_ord,  ford(bmin));
        atomicMax(&g_maxU_ord, ford(bmax));
    }
}

// ---------- k_exp: mask + exp + partial sums (finalize min/max inline) ----------
__global__ void __launch_bounds__(256) k_exp(const int* __restrict__ sel,
                                             float* __restrict__ out) {
    __shared__ float rs[8];
    int t = threadIdx.x;
    int e = blockIdx.x * 256 + t;
    float mn = orf(g_min_ord);
    float mx = fmaxf(mn, orf(g_maxU_ord));
    float s = g_scores[e];
    if (sel[e] != 0) s = mn;
    float v = ex2a((s - mx) * (2.0f * L2E));
    out[e] = v;
#pragma unroll
    for (int o = 16; o > 0; o >>= 1) v += __shfl_xor_sync(0xffffffffu, v, o);
    if ((t & 31) == 0) rs[t >> 5] = v;
    __syncthreads();
    if (t == 0) {
        float bs = rs[0];
#pragma unroll
        for (int i = 1; i < 8; i++) bs += rs[i];
        atomicAdd(&g_sum, bs);
    }
}

// ---------- k_scale ----------
__global__ void __launch_bounds__(256) k_scale(float* __restrict__ out) {
    int i = blockIdx.x * 256 + threadIdx.x;   // in float4 units
    float inv = 1.0f / g_sum;
    float4* o4 = (float4*)out;
    float4 v = o4[i];
    v.x *= inv; v.y *= inv; v.z *= inv; v.w *= inv;
    o4[i] = v;
}

// ---------- launch ----------
extern "C" void kernel_launch(void* const* d_in, const int* in_sizes, int n_in,
                              void* d_out, int out_size) {
    const float* node_reps = (const float*)d_in[0];
    const float* edge_reps = (const float*)d_in[1];
    const float* graph_rep = (const float*)d_in[2];
    const float* sub_rep   = (const float*)d_in[3];
    const float* W         = (const float*)d_in[4];
    const float* b         = (const float*)d_in[5];
    const int*   ei        = (const int*)d_in[6];
    const int*   sel       = (const int*)d_in[7];
    float* out = (float*)d_out;

    k_node<<<(NN + 255) / 256, 256>>>(node_reps, W);
    k_edge<<<NE / (EWARPS * 64), 128>>>(edge_reps, ei, sel, W, b, graph_rep, sub_rep);
    k_exp<<<NE / 256, 256>>>(sel, out);
    k_scale<<<NE / 1024, 256>>>(out);
}